// round 11
// baseline (speedup 1.0000x reference)
#include <cuda_runtime.h>
#include <cstdint>

#define SQRT2F 1.41421356237309515f
#define INV_SQRT2F 0.70710678118654752f

// ---------------- scratch ----------------
__device__ float g_xr [8u*256u*64u*64u];     // rna(x), conv1 A source
__device__ float g_y  [8u*256u*64u*64u];     // conv1 output (lrelu'd), f32
__device__ float g_up [8u*256u*128u*128u];   // rna(bilerp(g_y)), conv2 A source
__device__ float g_wB1[72u*256u*32u];        // conv1 B chunks [chunk][co][32 slot-permuted]
__device__ float g_wB2[80u*128u*32u];        // conv2+skip B chunks

// ---------------- helpers ----------------
__device__ __forceinline__ float rna_tf32(float x) {
    uint32_t r;
    asm("cvt.rna.tf32.f32 %0, %1;" : "=r"(r) : "f"(x));
    return __uint_as_float(r);
}
__device__ __forceinline__ void mma16888(float* c, const uint32_t* a, const uint32_t* b) {
    asm volatile(
        "mma.sync.aligned.m16n8k8.row.col.f32.tf32.tf32.f32 "
        "{%0,%1,%2,%3}, {%4,%5,%6,%7}, {%8,%9}, {%0,%1,%2,%3};"
        : "+f"(c[0]), "+f"(c[1]), "+f"(c[2]), "+f"(c[3])
        : "r"(a[0]), "r"(a[1]), "r"(a[2]), "r"(a[3]), "r"(b[0]), "r"(b[1]));
}
__device__ __forceinline__ void cp_a4(uint32_t dst, const float* src, bool ok) {
    int sz = ok ? 4 : 0;
    asm volatile("cp.async.ca.shared.global [%0], [%1], 4, %2;"
                 :: "r"(dst), "l"(src), "r"(sz));
}
__device__ __forceinline__ void cp_b16(uint32_t dst, const float4* src) {
    asm volatile("cp.async.cg.shared.global [%0], [%1], 16;" :: "r"(dst), "l"(src));
}
#define CP_COMMIT() asm volatile("cp.async.commit_group;" ::: "memory")
#define CP_WAIT0()  asm volatile("cp.async.wait_group 0;" ::: "memory")

// bilinear 2x coefficients (half-pixel, edge-clamped), 64 -> 128
__device__ __forceinline__ void up_coef(int o, int& i0, int& i1, float& f0, float& f1) {
    int m = o >> 1;
    if (o & 1) { i0 = m; i1 = (m + 1 < 64) ? m + 1 : 63; f0 = 0.75f; f1 = 0.25f; }
    else       { i0 = (m > 0) ? m - 1 : 0; i1 = m;       f0 = 0.25f; f1 = 0.75f; }
}

// ---------------- input pre-round: g_xr = rna(x) ----------------
__global__ __launch_bounds__(256)
void round_x(const float* __restrict__ x, float* __restrict__ xr) {
    int i = blockIdx.x * 256 + threadIdx.x;
    float4 v = *(const float4*)&x[i * 4];
    float4 o;
    o.x = rna_tf32(v.x); o.y = rna_tf32(v.y);
    o.z = rna_tf32(v.z); o.w = rna_tf32(v.w);
    *(float4*)&xr[i * 4] = o;
}

// ---------------- weight prep: scale fold + rna(tf32) + slot permutation ----------------
__global__ void prep_w(const float* __restrict__ w1, const float* __restrict__ w2,
                       const float* __restrict__ wsk) {
    int e = blockIdx.x * 256 + threadIdx.x;
    const float s3 = 1.0f / 48.0f;   // 1/sqrt(256*9)
    const float s1 = 0.0625f;        // 1/sqrt(256)
    if (e < 72 * 256 * 32) {
        int i   = e >> 13;
        int rem = e & 8191;
        int co  = rem >> 5;
        int kk  = rem & 31;
        int cb = i / 9, tap = i % 9;
        float v = w1[((size_t)co * 256 + (cb * 32 + kk)) * 9 + tap] * s3;
        int k8 = kk & 7;
        int off = co * 32 + (kk >> 3) * 8 + 2 * (k8 & 3) + (k8 >> 2);
        g_wB1[(size_t)i * 8192 + off] = rna_tf32(v);
    }
    if (e < 80 * 128 * 32) {
        int i   = e >> 12;
        int rem = e & 4095;
        int co  = rem >> 5;
        int kk  = rem & 31;
        float v;
        if (i < 72) {
            int cb = i / 9, tap = i % 9;
            v = w2[((size_t)co * 256 + (cb * 32 + kk)) * 9 + tap] * s3;
        } else {
            v = wsk[(size_t)co * 256 + ((i - 72) * 32 + kk)] * s1;
        }
        int k8 = kk & 7;
        int off = co * 32 + (kk >> 3) * 8 + 2 * (k8 & 3) + (k8 >> 2);
        g_wB2[(size_t)i * 4096 + off] = rna_tf32(v);
    }
}

// ---------------- fast bilinear 2x upsample, output pre-rounded to tf32 ----------------
__global__ __launch_bounds__(256)
void upsample2x_fast(const float* __restrict__ in, float* __restrict__ out) {
    int idx = blockIdx.x * 256 + threadIdx.x;
    int qw = idx & 31;
    int oh = (idx >> 5) & 127;
    int nc = idx >> 12;

    int ih0, ih1; float fh0, fh1;
    up_coef(oh, ih0, ih1, fh0, fh1);

    int c0 = (2 * qw - 1 > 0) ? 2 * qw - 1 : 0;
    int c1 = 2 * qw;
    int c2 = (2 * qw + 1 < 63) ? 2 * qw + 1 : 63;
    int c3 = (2 * qw + 2 < 63) ? 2 * qw + 2 : 63;

    const float* p  = in + (size_t)nc * 4096;
    const float* r0 = p + ih0 * 64;
    const float* r1 = p + ih1 * 64;
    float v0 = fh0 * r0[c0] + fh1 * r1[c0];
    float v1 = fh0 * r0[c1] + fh1 * r1[c1];
    float v2 = fh0 * r0[c2] + fh1 * r1[c2];
    float v3 = fh0 * r0[c3] + fh1 * r1[c3];

    float4 o;
    o.x = rna_tf32(0.25f * v0 + 0.75f * v1);
    o.y = rna_tf32(0.75f * v1 + 0.25f * v2);
    o.z = rna_tf32(0.25f * v1 + 0.75f * v2);
    o.w = rna_tf32(0.75f * v2 + 0.25f * v3);
    *(float4*)&out[(size_t)nc * 16384 + oh * 128 + 4 * qw] = o;
}

// ---------------- tf32 mma.sync implicit-GEMM conv, cp.async staging ----------------
// CTA: M=256 pixels x N=128 co, 512 threads = 16 warps (8 M x 2 N), warp tile 32x64.
// A smem: [32 slots][264]; B smem: [128 co][40]. Double buffered, cp.async pipelined.
// Sources are pre-rounded to tf32 (g_xr / g_up / weights) so staging is a pure copy.
// CONV2: 8 skip chunks (bilinear up(x) on the fly) keep the register staging path.
template<bool CONV1>
__global__ __launch_bounds__(512, 1)
void conv_mma(const float* __restrict__ in, const float* __restrict__ skipin,
              const float* __restrict__ wB, const float* __restrict__ bias,
              float* __restrict__ out)
{
    constexpr int COUT_TOT = CONV1 ? 256 : 128;
    constexpr int H = CONV1 ? 64 : 128;      // output dims (= main-source dims)
    constexpr int W = H;
    constexpr int HW = H * W;
    constexpr int HWs = 64 * 64;             // skip source (x) plane
    constexpr int NC = CONV1 ? 72 : 80;
    constexpr int AW   = 264;                // A row width (256 pixels + pad)
    constexpr int ABUF = 32 * AW;            // words
    constexpr int BBUF = 128 * 40;           // words

    extern __shared__ float smem[];
    const uint32_t sbase = (uint32_t)__cvta_generic_to_shared(smem);
    float* sA0 = smem;
    float* sB0 = smem + 2 * ABUF;

    const int tid  = threadIdx.x;
    const int lane = tid & 31;
    const int wid  = tid >> 5;
    const int g    = lane >> 2;
    const int t    = lane & 3;
    const int mbase = (wid & 7) * 32;
    const int Nb    = (wid >> 3) * 64;
    const int n   = blockIdx.z;
    const int h0  = CONV1 ? (blockIdx.x * 4) : (blockIdx.x * 2);
    const int co0 = CONV1 ? (blockIdx.y * 128) : 0;

    float acc[2][8][4];
    #pragma unroll
    for (int mt = 0; mt < 2; mt++)
        #pragma unroll
        for (int nt = 0; nt < 8; nt++)
            #pragma unroll
            for (int i = 0; i < 4; i++) acc[mt][nt][i] = 0.0f;

    const int sp = tid & 255;                 // staged pixel 0..255
    const int q  = tid >> 8;                  // 0..1 (channel half)
    const int sh = CONV1 ? (h0 + (sp >> 6)) : (h0 + (sp >> 7));
    const int sw = CONV1 ? (sp & 63) : (sp & 127);

    // ---- async-stage a main chunk (A via 16x cp.async.4B zfill, B via 2x cp.async.16B) ----
    auto cp_stage = [&](int c, int bsel) {
        int c0 = (c / 9) * 32;
        int tap = c % 9;
        const int oh = sh + tap / 3 - 1, ow = sw + tap % 3 - 1;
        const bool ok = (oh >= 0 && oh < H && ow >= 0 && ow < W);
        const float* base = in + ((size_t)n * 256 + c0) * HW + oh * W + ow;
        const uint32_t abase = sbase + (uint32_t)(bsel * ABUF) * 4;
        #pragma unroll
        for (int j = 0; j < 16; j++) {
            int kk = q * 16 + j;
            int k8 = kk & 7;
            int slot = (kk >> 3) * 8 + 2 * (k8 & 3) + (k8 >> 2);
            cp_a4(abase + (uint32_t)(slot * AW + sp) * 4, base + (size_t)kk * HW, ok);
        }
        const float4* wp = (const float4*)(wB + (size_t)c * (COUT_TOT * 32) + (size_t)co0 * 32);
        const uint32_t bbase = sbase + (uint32_t)(2 * ABUF + bsel * BBUF) * 4;
        cp_b16(bbase + (uint32_t)(((tid) >> 3) * 40 + (tid & 7) * 4) * 4, wp + tid);
        int f2 = tid + 512;
        cp_b16(bbase + (uint32_t)((f2 >> 3) * 40 + (f2 & 7) * 4) * 4, wp + f2);
    };

    // ---- skip chunk staging (conv2 only): registers + bilerp + rna ----
    float2 ar[8];
    auto ldg_skip = [&](int c) {
        int c0 = (c - 72) * 32;
        const int oh = sh, ow = sw;     // 1x1 tap, always in-bounds
        int hi0, hi1, wi0, wi1; float fh0, fh1, fw0, fw1;
        up_coef(oh, hi0, hi1, fh0, fh1);
        up_coef(ow, wi0, wi1, fw0, fw1);
        const int o00 = hi0 * 64 + wi0, o01 = hi0 * 64 + wi1;
        const int o10 = hi1 * 64 + wi0, o11 = hi1 * 64 + wi1;
        const float w00 = fh0 * fw0, w01 = fh0 * fw1;
        const float w10 = fh1 * fw0, w11 = fh1 * fw1;
        const float* basep = skipin + ((size_t)n * 256 + c0) * HWs;
        #pragma unroll
        for (int j = 0; j < 8; j++) {
            int pp = q * 8 + j;
            int k0 = (pp >> 2) * 8 + (pp & 3);
            const float* p0 = basep + (size_t)k0 * HWs;
            const float* p1 = p0 + (size_t)4 * HWs;
            float v0 = w00 * p0[o00] + w01 * p0[o01] + w10 * p0[o10] + w11 * p0[o11];
            float v1 = w00 * p1[o00] + w01 * p1[o01] + w10 * p1[o10] + w11 * p1[o11];
            ar[j] = make_float2(rna_tf32(v0), rna_tf32(v1));
        }
    };
    auto sts_skip = [&](int c, int bsel) {
        float* sA = sA0 + bsel * ABUF;
        #pragma unroll
        for (int j = 0; j < 8; j++) {
            int pp = q * 8 + j;
            int s0 = (pp >> 2) * 8 + 2 * (pp & 3);
            sA[s0 * AW + sp]       = ar[j].x;
            sA[(s0 + 1) * AW + sp] = ar[j].y;
        }
        // B for skip chunk: plain LDG/STS (cheap, 8 chunks only)
        const float4* wp = (const float4*)(wB + (size_t)c * (COUT_TOT * 32));
        float* sB = sB0 + bsel * BBUF;
        float4 b0 = wp[tid];
        float4 b1 = wp[tid + 512];
        *(float4*)&sB[(tid >> 3) * 40 + (tid & 7) * 4] = b0;
        int f2 = tid + 512;
        *(float4*)&sB[(f2 >> 3) * 40 + (f2 & 7) * 4] = b1;
    };

    // prologue: stage chunk 0
    cp_stage(0, 0);
    CP_COMMIT();
    CP_WAIT0();
    __syncthreads();

    for (int cc = 0; cc < NC; cc++) {
        const bool have_next = (cc + 1 < NC);
        const bool next_main = have_next && (CONV1 || cc + 1 < 72);
        if (next_main) { cp_stage(cc + 1, (cc + 1) & 1); CP_COMMIT(); }
        else if (have_next) ldg_skip(cc + 1);

        const float* sA = sA0 + (cc & 1) * ABUF;
        const float* sB = sB0 + (cc & 1) * BBUF;
        #pragma unroll
        for (int ks = 0; ks < 4; ks++) {
            uint32_t a[2][4];
            uint32_t b[8][2];
            const int sb0 = (ks * 8 + 2 * t) * AW;
            #pragma unroll
            for (int mt = 0; mt < 2; mt++) {
                int r0 = mbase + mt * 16 + g;
                a[mt][0] = __float_as_uint(sA[sb0 + r0]);
                a[mt][1] = __float_as_uint(sA[sb0 + r0 + 8]);
                a[mt][2] = __float_as_uint(sA[sb0 + AW + r0]);
                a[mt][3] = __float_as_uint(sA[sb0 + AW + r0 + 8]);
            }
            #pragma unroll
            for (int nt = 0; nt < 8; nt++) {
                float2 bb = *(const float2*)&sB[(Nb + nt * 8 + g) * 40 + ks * 8 + 2 * t];
                b[nt][0] = __float_as_uint(bb.x);
                b[nt][1] = __float_as_uint(bb.y);
            }
            #pragma unroll
            for (int mt = 0; mt < 2; mt++)
                #pragma unroll
                for (int nt = 0; nt < 8; nt++)
                    mma16888(acc[mt][nt], a[mt], b[nt]);
        }

        // conv2: after the 72 main chunks, bias+lrelu accumulators; skip chunks add on top
        if (!CONV1 && cc == 71) {
            #pragma unroll
            for (int nt = 0; nt < 8; nt++) {
                int col = co0 + Nb + nt * 8 + 2 * t;
                float b0 = __ldg(&bias[col]), b1 = __ldg(&bias[col + 1]);
                #pragma unroll
                for (int mt = 0; mt < 2; mt++)
                    #pragma unroll
                    for (int i = 0; i < 4; i++) {
                        float y = acc[mt][nt][i] + ((i & 1) ? b1 : b0);
                        acc[mt][nt][i] = (y >= 0.f ? y : 0.2f * y) * SQRT2F;
                    }
            }
        }

        if (have_next) {
            if (!next_main) sts_skip(cc + 1, (cc + 1) & 1);
            CP_WAIT0();
            __syncthreads();
        }
    }

    // ---- epilogue ----
    #pragma unroll
    for (int nt = 0; nt < 8; nt++) {
        int colb = co0 + Nb + nt * 8 + 2 * t;
        float b0 = 0.f, b1 = 0.f;
        if (CONV1) { b0 = __ldg(&bias[colb]); b1 = __ldg(&bias[colb + 1]); }
        #pragma unroll
        for (int mt = 0; mt < 2; mt++)
            #pragma unroll
            for (int i = 0; i < 4; i++) {
                int m   = mbase + mt * 16 + g + ((i >> 1) << 3);
                int col = colb + (i & 1);
                int h = CONV1 ? (h0 + (m >> 6)) : (h0 + (m >> 7));
                int w = CONV1 ? (m & 63) : (m & 127);
                size_t addr = ((size_t)n * COUT_TOT + col) * HW + (size_t)h * W + w;
                if (CONV1) {
                    float y = acc[mt][nt][i] + ((i & 1) ? b1 : b0);
                    out[addr] = (y >= 0.f ? y : 0.2f * y) * SQRT2F;
                } else {
                    out[addr] = acc[mt][nt][i] * INV_SQRT2F;
                }
            }
    }
}

// ---------------- launch ----------------
extern "C" void kernel_launch(void* const* d_in, const int* in_sizes, int n_in,
                              void* d_out, int out_size) {
    const float* x   = (const float*)d_in[0];
    const float* w1  = (const float*)d_in[1];
    const float* b1  = (const float*)d_in[2];
    const float* w2  = (const float*)d_in[3];
    const float* b2  = (const float*)d_in[4];
    const float* wsk = (const float*)d_in[5];
    float* out = (float*)d_out;

    float *p_xr, *p_y, *p_up, *p_wB1, *p_wB2;
    cudaGetSymbolAddress((void**)&p_xr,  g_xr);
    cudaGetSymbolAddress((void**)&p_y,   g_y);
    cudaGetSymbolAddress((void**)&p_up,  g_up);
    cudaGetSymbolAddress((void**)&p_wB1, g_wB1);
    cudaGetSymbolAddress((void**)&p_wB2, g_wB2);

    constexpr int SMEM = (2 * 32 * 264 + 2 * 128 * 40) * 4;   // 108544 B
    cudaFuncSetAttribute(conv_mma<true>,  cudaFuncAttributeMaxDynamicSharedMemorySize, SMEM);
    cudaFuncSetAttribute(conv_mma<false>, cudaFuncAttributeMaxDynamicSharedMemorySize, SMEM);

    // 0) weight prep + input pre-round
    prep_w<<<2304, 256>>>(w1, w2, wsk);
    round_x<<<(8 * 256 * 64 * 64) / 1024, 256>>>(x, p_xr);

    // 1) conv1 (256->256 @64x64) + lrelu -> g_y   [A from pre-rounded g_xr]
    conv_mma<true><<<dim3(16, 2, 8), 512, SMEM>>>(p_xr, nullptr, p_wB1, b1, p_y);

    // 2) fast bilinear upsample g_y -> g_up (pre-rounded tf32)
    upsample2x_fast<<<(8 * 256 * 128 * 32) / 256, 256>>>(p_y, p_up);

    // 3) conv2 (256->128 @128x128) on g_up + lrelu + fused on-the-fly skip from raw x -> out
    conv_mma<false><<<dim3(64, 1, 8), 512, SMEM>>>(p_up, x, p_wB2, b2, out);
}

// round 12
// speedup vs baseline: 1.1436x; 1.1436x over previous
#include <cuda_runtime.h>
#include <cstdint>

#define SQRT2F 1.41421356237309515f
#define INV_SQRT2F 0.70710678118654752f

// ---------------- scratch ----------------
__device__ float g_xr [8u*256u*64u*64u];     // rna(x), conv1 A source
__device__ float g_y  [8u*256u*64u*64u];     // conv1 output (lrelu'd), f32
__device__ float g_up [8u*256u*128u*128u];   // rna(bilerp(g_y)), conv2 A source
__device__ float g_wB1[72u*256u*32u];        // conv1 B chunks [chunk][co][32 slot-permuted]
__device__ float g_wB2[80u*128u*32u];        // conv2+skip B chunks

// ---------------- helpers ----------------
__device__ __forceinline__ float rna_tf32(float x) {
    uint32_t r;
    asm("cvt.rna.tf32.f32 %0, %1;" : "=r"(r) : "f"(x));
    return __uint_as_float(r);
}
__device__ __forceinline__ void mma16888(float* c, const uint32_t* a, const uint32_t* b) {
    asm volatile(
        "mma.sync.aligned.m16n8k8.row.col.f32.tf32.tf32.f32 "
        "{%0,%1,%2,%3}, {%4,%5,%6,%7}, {%8,%9}, {%0,%1,%2,%3};"
        : "+f"(c[0]), "+f"(c[1]), "+f"(c[2]), "+f"(c[3])
        : "r"(a[0]), "r"(a[1]), "r"(a[2]), "r"(a[3]), "r"(b[0]), "r"(b[1]));
}
__device__ __forceinline__ void cp_b16(uint32_t dst, const float4* src) {
    asm volatile("cp.async.cg.shared.global [%0], [%1], 16;" :: "r"(dst), "l"(src));
}
#define CP_COMMIT() asm volatile("cp.async.commit_group;" ::: "memory")
#define CP_WAIT0()  asm volatile("cp.async.wait_group 0;" ::: "memory")

// bilinear 2x coefficients (half-pixel, edge-clamped), 64 -> 128
__device__ __forceinline__ void up_coef(int o, int& i0, int& i1, float& f0, float& f1) {
    int m = o >> 1;
    if (o & 1) { i0 = m; i1 = (m + 1 < 64) ? m + 1 : 63; f0 = 0.75f; f1 = 0.25f; }
    else       { i0 = (m > 0) ? m - 1 : 0; i1 = m;       f0 = 0.25f; f1 = 0.75f; }
}

// ---------------- input pre-round: g_xr = rna(x) ----------------
__global__ __launch_bounds__(256)
void round_x(const float* __restrict__ x, float* __restrict__ xr) {
    int i = blockIdx.x * 256 + threadIdx.x;
    float4 v = *(const float4*)&x[i * 4];
    float4 o;
    o.x = rna_tf32(v.x); o.y = rna_tf32(v.y);
    o.z = rna_tf32(v.z); o.w = rna_tf32(v.w);
    *(float4*)&xr[i * 4] = o;
}

// ---------------- weight prep: scale fold + rna(tf32) + slot permutation ----------------
__global__ void prep_w(const float* __restrict__ w1, const float* __restrict__ w2,
                       const float* __restrict__ wsk) {
    int e = blockIdx.x * 256 + threadIdx.x;
    const float s3 = 1.0f / 48.0f;   // 1/sqrt(256*9)
    const float s1 = 0.0625f;        // 1/sqrt(256)
    if (e < 72 * 256 * 32) {
        int i   = e >> 13;
        int rem = e & 8191;
        int co  = rem >> 5;
        int kk  = rem & 31;
        int cb = i / 9, tap = i % 9;
        float v = w1[((size_t)co * 256 + (cb * 32 + kk)) * 9 + tap] * s3;
        int k8 = kk & 7;
        int off = co * 32 + (kk >> 3) * 8 + 2 * (k8 & 3) + (k8 >> 2);
        g_wB1[(size_t)i * 8192 + off] = rna_tf32(v);
    }
    if (e < 80 * 128 * 32) {
        int i   = e >> 12;
        int rem = e & 4095;
        int co  = rem >> 5;
        int kk  = rem & 31;
        float v;
        if (i < 72) {
            int cb = i / 9, tap = i % 9;
            v = w2[((size_t)co * 256 + (cb * 32 + kk)) * 9 + tap] * s3;
        } else {
            v = wsk[(size_t)co * 256 + ((i - 72) * 32 + kk)] * s1;
        }
        int k8 = kk & 7;
        int off = co * 32 + (kk >> 3) * 8 + 2 * (k8 & 3) + (k8 >> 2);
        g_wB2[(size_t)i * 4096 + off] = rna_tf32(v);
    }
}

// ---------------- fast bilinear 2x upsample, output pre-rounded to tf32 ----------------
__global__ __launch_bounds__(256)
void upsample2x_fast(const float* __restrict__ in, float* __restrict__ out) {
    int idx = blockIdx.x * 256 + threadIdx.x;
    int qw = idx & 31;
    int oh = (idx >> 5) & 127;
    int nc = idx >> 12;

    int ih0, ih1; float fh0, fh1;
    up_coef(oh, ih0, ih1, fh0, fh1);

    int c0 = (2 * qw - 1 > 0) ? 2 * qw - 1 : 0;
    int c1 = 2 * qw;
    int c2 = (2 * qw + 1 < 63) ? 2 * qw + 1 : 63;
    int c3 = (2 * qw + 2 < 63) ? 2 * qw + 2 : 63;

    const float* p  = in + (size_t)nc * 4096;
    const float* r0 = p + ih0 * 64;
    const float* r1 = p + ih1 * 64;
    float v0 = fh0 * r0[c0] + fh1 * r1[c0];
    float v1 = fh0 * r0[c1] + fh1 * r1[c1];
    float v2 = fh0 * r0[c2] + fh1 * r1[c2];
    float v3 = fh0 * r0[c3] + fh1 * r1[c3];

    float4 o;
    o.x = rna_tf32(0.25f * v0 + 0.75f * v1);
    o.y = rna_tf32(0.75f * v1 + 0.25f * v2);
    o.z = rna_tf32(0.25f * v1 + 0.75f * v2);
    o.w = rna_tf32(0.75f * v2 + 0.25f * v3);
    *(float4*)&out[(size_t)nc * 16384 + oh * 128 + 4 * qw] = o;
}

// ---------------- tf32 mma.sync implicit-GEMM conv ----------------
// CTA: M=256 pixels x N=128 co, 512 threads = 16 warps (8 M x 2 N), warp tile 32x64.
// A smem: [32 slots][260] (AW=260 -> fragment banks 8t+g: conflict-free).
// B smem: [128 co][40], staged via cp.async.cg 16B. Double buffered.
// A staged via LDG.32 from pre-rounded sources (no cvt) + STS.32.
// CONV2: 8 skip chunks compute bilinear up(x) on the fly into registers.
template<bool CONV1>
__global__ __launch_bounds__(512, 1)
void conv_mma(const float* __restrict__ in, const float* __restrict__ skipin,
              const float* __restrict__ wB, const float* __restrict__ bias,
              float* __restrict__ out)
{
    constexpr int COUT_TOT = CONV1 ? 256 : 128;
    constexpr int H = CONV1 ? 64 : 128;      // output dims (= main-source dims)
    constexpr int W = H;
    constexpr int HW = H * W;
    constexpr int HWs = 64 * 64;             // skip source (x) plane
    constexpr int NC = CONV1 ? 72 : 80;
    constexpr int AW   = 260;                // A row width (256 pixels + pad 4)
    constexpr int ABUF = 32 * AW;            // 8320 words
    constexpr int BBUF = 128 * 40;           // 5120 words

    extern __shared__ float smem[];
    const uint32_t sbase = (uint32_t)__cvta_generic_to_shared(smem);
    float* sA0 = smem;
    float* sB0 = smem + 2 * ABUF;

    const int tid  = threadIdx.x;
    const int lane = tid & 31;
    const int wid  = tid >> 5;
    const int g    = lane >> 2;
    const int t    = lane & 3;
    const int mbase = (wid & 7) * 32;
    const int Nb    = (wid >> 3) * 64;
    const int n   = blockIdx.z;
    const int h0  = CONV1 ? (blockIdx.x * 4) : (blockIdx.x * 2);
    const int co0 = CONV1 ? (blockIdx.y * 128) : 0;

    float acc[2][8][4];
    #pragma unroll
    for (int mt = 0; mt < 2; mt++)
        #pragma unroll
        for (int nt = 0; nt < 8; nt++)
            #pragma unroll
            for (int i = 0; i < 4; i++) acc[mt][nt][i] = 0.0f;

    float2 ar[8];
    const int sp = tid & 255;                 // staged pixel 0..255
    const int q  = tid >> 8;                  // 0..1 (channel half)
    const int sh = CONV1 ? (h0 + (sp >> 6)) : (h0 + (sp >> 7));
    const int sw = CONV1 ? (sp & 63) : (sp & 127);

    // ---- B: async 16B stage for any chunk ----
    auto stage_b = [&](int c, int bsel) {
        const float4* wp = (const float4*)(wB + (size_t)c * (COUT_TOT * 32) + (size_t)co0 * 32);
        const uint32_t bbase = sbase + (uint32_t)(2 * ABUF + bsel * BBUF) * 4;
        cp_b16(bbase + (uint32_t)((tid >> 3) * 40 + (tid & 7) * 4) * 4, wp + tid);
        int f2 = tid + 512;
        cp_b16(bbase + (uint32_t)((f2 >> 3) * 40 + (f2 & 7) * 4) * 4, wp + f2);
    };

    // ---- A: LDG into registers (sources pre-rounded; no cvt) ----
    auto ldg_a = [&](int c) {
        const bool isskip = (!CONV1) && (c >= 72);
        if (!isskip) {
            int c0 = (c / 9) * 32;
            int tap = c % 9;
            const int oh = sh + tap / 3 - 1, ow = sw + tap % 3 - 1;
            const bool ok = (oh >= 0 && oh < H && ow >= 0 && ow < W);
            const float* base = in + ((size_t)n * 256 + c0) * HW + oh * W + ow;
            #pragma unroll
            for (int j = 0; j < 8; j++) {
                int pp = q * 8 + j;           // pair index 0..15
                int k0 = (pp >> 2) * 8 + (pp & 3);
                float v0 = 0.f, v1 = 0.f;
                if (ok) {
                    v0 = base[(size_t)k0 * HW];
                    v1 = base[(size_t)(k0 + 4) * HW];
                }
                ar[j] = make_float2(v0, v1);
            }
        } else {
            int c0 = (c - 72) * 32;
            int hi0, hi1, wi0, wi1; float fh0, fh1, fw0, fw1;
            up_coef(sh, hi0, hi1, fh0, fh1);
            up_coef(sw, wi0, wi1, fw0, fw1);
            const int o00 = hi0 * 64 + wi0, o01 = hi0 * 64 + wi1;
            const int o10 = hi1 * 64 + wi0, o11 = hi1 * 64 + wi1;
            const float w00 = fh0 * fw0, w01 = fh0 * fw1;
            const float w10 = fh1 * fw0, w11 = fh1 * fw1;
            const float* basep = skipin + ((size_t)n * 256 + c0) * HWs;
            #pragma unroll
            for (int j = 0; j < 8; j++) {
                int pp = q * 8 + j;
                int k0 = (pp >> 2) * 8 + (pp & 3);
                const float* p0 = basep + (size_t)k0 * HWs;
                const float* p1 = p0 + (size_t)4 * HWs;
                float v0 = w00 * p0[o00] + w01 * p0[o01] + w10 * p0[o10] + w11 * p0[o11];
                float v1 = w00 * p1[o00] + w01 * p1[o01] + w10 * p1[o10] + w11 * p1[o11];
                ar[j] = make_float2(rna_tf32(v0), rna_tf32(v1));
            }
        }
    };
    auto sts_a = [&](int bsel) {
        float* sA = sA0 + bsel * ABUF;
        #pragma unroll
        for (int j = 0; j < 8; j++) {
            int pp = q * 8 + j;
            int s0 = (pp >> 2) * 8 + 2 * (pp & 3);
            sA[s0 * AW + sp]       = ar[j].x;
            sA[(s0 + 1) * AW + sp] = ar[j].y;
        }
    };

    // prologue: stage chunk 0
    stage_b(0, 0);
    CP_COMMIT();
    ldg_a(0);
    sts_a(0);
    CP_WAIT0();
    __syncthreads();

    for (int cc = 0; cc < NC; cc++) {
        const bool have_next = (cc + 1 < NC);
        if (have_next) {
            stage_b(cc + 1, (cc + 1) & 1);
            CP_COMMIT();
            ldg_a(cc + 1);                  // LDG latency hidden under compute
        }

        const float* sA = sA0 + (cc & 1) * ABUF;
        const float* sB = sB0 + (cc & 1) * BBUF;
        #pragma unroll
        for (int ks = 0; ks < 4; ks++) {
            uint32_t a[2][4];
            uint32_t b[8][2];
            const int sb0 = (ks * 8 + 2 * t) * AW;
            #pragma unroll
            for (int mt = 0; mt < 2; mt++) {
                int r0 = mbase + mt * 16 + g;
                a[mt][0] = __float_as_uint(sA[sb0 + r0]);
                a[mt][1] = __float_as_uint(sA[sb0 + r0 + 8]);
                a[mt][2] = __float_as_uint(sA[sb0 + AW + r0]);
                a[mt][3] = __float_as_uint(sA[sb0 + AW + r0 + 8]);
            }
            #pragma unroll
            for (int nt = 0; nt < 8; nt++) {
                float2 bb = *(const float2*)&sB[(Nb + nt * 8 + g) * 40 + ks * 8 + 2 * t];
                b[nt][0] = __float_as_uint(bb.x);
                b[nt][1] = __float_as_uint(bb.y);
            }
            #pragma unroll
            for (int mt = 0; mt < 2; mt++)
                #pragma unroll
                for (int nt = 0; nt < 8; nt++)
                    mma16888(acc[mt][nt], a[mt], b[nt]);
        }

        // conv2: after the 72 main chunks, bias+lrelu accumulators; skip chunks add on top
        if (!CONV1 && cc == 71) {
            #pragma unroll
            for (int nt = 0; nt < 8; nt++) {
                int col = co0 + Nb + nt * 8 + 2 * t;
                float b0 = __ldg(&bias[col]), b1 = __ldg(&bias[col + 1]);
                #pragma unroll
                for (int mt = 0; mt < 2; mt++)
                    #pragma unroll
                    for (int i = 0; i < 4; i++) {
                        float y = acc[mt][nt][i] + ((i & 1) ? b1 : b0);
                        acc[mt][nt][i] = (y >= 0.f ? y : 0.2f * y) * SQRT2F;
                    }
            }
        }

        if (have_next) {
            sts_a((cc + 1) & 1);
            CP_WAIT0();
            __syncthreads();
        }
    }

    // ---- epilogue ----
    #pragma unroll
    for (int nt = 0; nt < 8; nt++) {
        int colb = co0 + Nb + nt * 8 + 2 * t;
        float b0 = 0.f, b1 = 0.f;
        if (CONV1) { b0 = __ldg(&bias[colb]); b1 = __ldg(&bias[colb + 1]); }
        #pragma unroll
        for (int mt = 0; mt < 2; mt++)
            #pragma unroll
            for (int i = 0; i < 4; i++) {
                int m   = mbase + mt * 16 + g + ((i >> 1) << 3);
                int col = colb + (i & 1);
                int h = CONV1 ? (h0 + (m >> 6)) : (h0 + (m >> 7));
                int w = CONV1 ? (m & 63) : (m & 127);
                size_t addr = ((size_t)n * COUT_TOT + col) * HW + (size_t)h * W + w;
                if (CONV1) {
                    float y = acc[mt][nt][i] + ((i & 1) ? b1 : b0);
                    out[addr] = (y >= 0.f ? y : 0.2f * y) * SQRT2F;
                } else {
                    out[addr] = acc[mt][nt][i] * INV_SQRT2F;
                }
            }
    }
}

// ---------------- launch ----------------
extern "C" void kernel_launch(void* const* d_in, const int* in_sizes, int n_in,
                              void* d_out, int out_size) {
    const float* x   = (const float*)d_in[0];
    const float* w1  = (const float*)d_in[1];
    const float* b1  = (const float*)d_in[2];
    const float* w2  = (const float*)d_in[3];
    const float* b2  = (const float*)d_in[4];
    const float* wsk = (const float*)d_in[5];
    float* out = (float*)d_out;

    float *p_xr, *p_y, *p_up, *p_wB1, *p_wB2;
    cudaGetSymbolAddress((void**)&p_xr,  g_xr);
    cudaGetSymbolAddress((void**)&p_y,   g_y);
    cudaGetSymbolAddress((void**)&p_up,  g_up);
    cudaGetSymbolAddress((void**)&p_wB1, g_wB1);
    cudaGetSymbolAddress((void**)&p_wB2, g_wB2);

    constexpr int SMEM = (2 * 32 * 260 + 2 * 128 * 40) * 4;   // 107520 B
    cudaFuncSetAttribute(conv_mma<true>,  cudaFuncAttributeMaxDynamicSharedMemorySize, SMEM);
    cudaFuncSetAttribute(conv_mma<false>, cudaFuncAttributeMaxDynamicSharedMemorySize, SMEM);

    // 0) weight prep + input pre-round
    prep_w<<<2304, 256>>>(w1, w2, wsk);
    round_x<<<(8 * 256 * 64 * 64) / 1024, 256>>>(x, p_xr);

    // 1) conv1 (256->256 @64x64) + lrelu -> g_y   [A from pre-rounded g_xr]
    conv_mma<true><<<dim3(16, 2, 8), 512, SMEM>>>(p_xr, nullptr, p_wB1, b1, p_y);

    // 2) fast bilinear upsample g_y -> g_up (pre-rounded tf32)
    upsample2x_fast<<<(8 * 256 * 128 * 32) / 256, 256>>>(p_y, p_up);

    // 3) conv2 (256->128 @128x128) on g_up + lrelu + fused on-the-fly skip from raw x -> out
    conv_mma<false><<<dim3(64, 1, 8), 512, SMEM>>>(p_up, x, p_wB2, b2, out);
}